// round 5
// baseline (speedup 1.0000x reference)
#include <cuda_runtime.h>
#include <cuda_fp16.h>

#define N_NODES 100000
#define N_EDGES 3200000
#define N_GRAPHS 1000
#define IN_DIM 10
#define HID 20
#define CAP 96
#define BN_EPS 1e-5f

#define TB 256
#define NBLK_N ((N_NODES + TB - 1) / TB)     // 391
#define MAXBLK 1563                          // ceil(100000/64)

// ---- device scratch ----
__device__ int    g_cur[N_NODES];
__device__ int    g_src[CAP * N_NODES];                // transposed: g_src[k*N + i]
__device__ __align__(128) __half g_xh[N_NODES * 16];   // x half rows, 10 -> 16 (32B)
__device__ __align__(128) __half g_hh[N_NODES * 32];   // h half rows, 20 -> 32 (64B, line-contained)
__device__ __align__(16)  float  g_tmp[N_NODES * HID]; // pre-BN activations (fp32)
__device__ float  g_bsum[MAXBLK * HID];
__device__ float  g_bsq[MAXBLK * HID];
__device__ float  g_ab[2 * HID];                       // folded BN: y*a + b

__global__ void k_zero_cur() {
    int i = blockIdx.x * blockDim.x + threadIdx.x;
    if (i < N_NODES) g_cur[i] = 0;
}

// 4 edges per thread via int4 loads
__global__ void k_fill4(const int* __restrict__ ei) {
    int e4 = blockIdx.x * blockDim.x + threadIdx.x;
    if (e4 * 4 >= N_EDGES) return;
    int4 s4 = ((const int4*)ei)[e4];
    int4 d4 = ((const int4*)(ei + N_EDGES))[e4];
    int ss[4] = {s4.x, s4.y, s4.z, s4.w};
    int dd[4] = {d4.x, d4.y, d4.z, d4.w};
#pragma unroll
    for (int q = 0; q < 4; q++) {
        int s = min(max(ss[q], 0), N_NODES - 1);
        int d = min(max(dd[q], 0), N_NODES - 1);
        int p = atomicAdd(&g_cur[d], 1);
        if (p < CAP) g_src[p * N_NODES + d] = s;
    }
}

// convert x (fp32, 10 dims) -> half rows padded to 16
__global__ void k_x2h(const float* __restrict__ x) {
    int i = blockIdx.x * blockDim.x + threadIdx.x;
    if (i >= N_NODES) return;
    const float2* xp = (const float2*)(x + (size_t)i * IN_DIM);
    __half2 h[8];
#pragma unroll
    for (int q = 0; q < 5; q++) { float2 v = xp[q]; h[q] = __floats2half2_rn(v.x, v.y); }
#pragma unroll
    for (int q = 5; q < 8; q++) h[q] = __floats2half2_rn(0.f, 0.f);
    int4* op = (int4*)(g_xh + (size_t)i * 16);
    op[0] = *(int4*)&h[0];
    op[1] = *(int4*)&h[4];
}

__device__ __forceinline__ void add_int4(float* acc, int4 v) {
    int w[4] = {v.x, v.y, v.z, v.w};
#pragma unroll
    for (int c = 0; c < 4; c++) {
        float2 f = __half22float2(*(__half2*)&w[c]);
        acc[c * 2]     += f.x;
        acc[c * 2 + 1] += f.y;
    }
}

// GRP lanes cooperate on one node. Lane sub owns dims [sub*8, sub*8+8).
// DR = real dims, DP = padded halfs per row (16 or 32), GRP = 2 or 4.
template <int DR, int DP, int GRP>
__global__ void k_gin(const float* __restrict__ W, const float* __restrict__ bias) {
    const int SWS = 21;  // padded stride kills 4-way LDS bank conflicts
    __shared__ float sW[32 * SWS];
    __shared__ float sb[HID];
    __shared__ float sws[8][HID];
    __shared__ float swq[8][HID];

    const __half* hin = (DR == IN_DIM) ? (const __half*)g_xh : (const __half*)g_hh;

    int t = threadIdx.x;
    for (int j = t; j < 32 * SWS; j += blockDim.x) sW[j] = 0.f;
    __syncthreads();
    for (int j = t; j < DR * HID; j += blockDim.x) {
        int d = j / HID, c = j % HID;
        sW[d * SWS + c] = W[j];
    }
    if (t < HID) sb[t] = bias[t];
    __syncthreads();

    int lane = t & 31, wwid = t >> 5;
    int sub = lane & (GRP - 1);
    const int NPW = 32 / GRP;                       // nodes per warp
    int i = blockIdx.x * (8 * NPW) + wwid * NPW + (lane / GRP);
    unsigned gmask = ((1u << GRP) - 1u) << (lane & ~(GRP - 1));

    float acc[8];
#pragma unroll
    for (int q = 0; q < 8; q++) acc[q] = 0.f;
    float y[HID];
#pragma unroll
    for (int j = 0; j < HID; j++) y[j] = 0.f;

    bool active = (i < N_NODES);
    const bool ld = (sub * 8 < DP);
    if (active) {
        if (ld) add_int4(acc, *(const int4*)(hin + (size_t)i * DP + sub * 8));
        int deg = min(g_cur[i], CAP);
        const int* sp = g_src + i;
        for (int k = 0; k < deg; k += GRP) {
            int kk = k + sub;
            int s = sp[min(kk, deg - 1) * N_NODES];
#pragma unroll
            for (int j = 0; j < GRP; j++) {
                if (k + j >= deg) break;
                int sj = __shfl_sync(gmask, s, j, GRP);
                if (ld) add_int4(acc, *(const int4*)(hin + (size_t)sj * DP + sub * 8));
            }
        }
        // distributed GEMV over this lane's dims, then combine across the group
#pragma unroll
        for (int j = 0; j < HID; j++) {
            float v = 0.f;
#pragma unroll
            for (int dl = 0; dl < 8; dl++)
                v += acc[dl] * sW[(sub * 8 + dl) * SWS + j];
#pragma unroll
            for (int o = GRP >> 1; o; o >>= 1)
                v += __shfl_xor_sync(gmask, v, o, GRP);
            y[j] = v + sb[j];
        }
        if (sub == 0) {
            float4* tp = (float4*)(g_tmp + (size_t)i * HID);
#pragma unroll
            for (int j = 0; j < 5; j++)
                tp[j] = make_float4(y[4*j], y[4*j+1], y[4*j+2], y[4*j+3]);
        }
    }
    if (!active || sub != 0) {
#pragma unroll
        for (int j = 0; j < HID; j++) y[j] = 0.f;
    }

    // BN stats: nonzero only on sub0 lanes; reduce across warp, then block
#pragma unroll
    for (int j = 0; j < HID; j++) {
        float s = y[j], q = y[j] * y[j];
#pragma unroll
        for (int o = 16; o >= GRP; o >>= 1) {
            s += __shfl_down_sync(0xffffffff, s, o);
            q += __shfl_down_sync(0xffffffff, q, o);
        }
        if (lane == 0) { sws[wwid][j] = s; swq[wwid][j] = q; }
    }
    __syncthreads();
    if (t < HID) {
        float s = 0.f, q = 0.f;
#pragma unroll
        for (int w = 0; w < 8; w++) { s += sws[w][t]; q += swq[w][t]; }
        g_bsum[blockIdx.x * HID + t] = s;
        g_bsq[blockIdx.x * HID + t]  = q;
    }
}

// parallel partial reduce: warp w handles channel w; nblk partials
__global__ void k_finalize(const float* __restrict__ g, const float* __restrict__ beta, int nblk) {
    int w = threadIdx.x >> 5, lane = threadIdx.x & 31;
    if (w >= HID) return;
    double s = 0.0, q = 0.0;
    for (int b = lane; b < nblk; b += 32) {
        s += (double)g_bsum[b * HID + w];
        q += (double)g_bsq[b * HID + w];
    }
#pragma unroll
    for (int o = 16; o; o >>= 1) {
        s += __shfl_down_sync(0xffffffff, s, o);
        q += __shfl_down_sync(0xffffffff, q, o);
    }
    if (lane == 0) {
        float mu  = (float)(s / (double)N_NODES);
        float var = (float)(q / (double)N_NODES) - mu * mu;
        float a = rsqrtf(var + BN_EPS) * g[w];
        g_ab[w] = a;
        g_ab[HID + w] = beta[w] - mu * a;
    }
}

// normalize + relu -> half rows padded to 32 (64B)
__global__ void k_norm() {
    int i = blockIdx.x * blockDim.x + threadIdx.x;
    if (i >= N_NODES) return;
    const float4* tp = (const float4*)(g_tmp + (size_t)i * HID);
    __half2 h[16];
#pragma unroll
    for (int q = 0; q < 5; q++) {
        float4 v = tp[q];
        int j = 4 * q;
        float r0 = fmaxf(v.x * g_ab[j+0] + g_ab[HID+j+0], 0.f);
        float r1 = fmaxf(v.y * g_ab[j+1] + g_ab[HID+j+1], 0.f);
        float r2 = fmaxf(v.z * g_ab[j+2] + g_ab[HID+j+2], 0.f);
        float r3 = fmaxf(v.w * g_ab[j+3] + g_ab[HID+j+3], 0.f);
        h[2*q]   = __floats2half2_rn(r0, r1);
        h[2*q+1] = __floats2half2_rn(r2, r3);
    }
#pragma unroll
    for (int q = 10; q < 16; q++) h[q] = __floats2half2_rn(0.f, 0.f);
    int4* op = (int4*)(g_hh + (size_t)i * 32);
    op[0] = *(int4*)&h[0];
    op[1] = *(int4*)&h[4];
    op[2] = *(int4*)&h[8];
    op[3] = *(int4*)&h[12];
}

// warp per graph: binary-search node range (batch sorted), norm+relu+pool+fc
__global__ void k_pool_fc(const int* __restrict__ batch,
                          const float* __restrict__ fcW, const float* __restrict__ fcb,
                          float* __restrict__ out) {
    int gid = (blockIdx.x * blockDim.x + threadIdx.x) >> 5;
    int lane = threadIdx.x & 31;
    if (gid >= N_GRAPHS) return;

    int lo = 0, hi = N_NODES;
    while (lo < hi) { int mid = (lo + hi) >> 1; if (batch[mid] < gid) lo = mid + 1; else hi = mid; }
    int r0 = lo;
    hi = N_NODES;
    while (lo < hi) { int mid = (lo + hi) >> 1; if (batch[mid] < gid + 1) lo = mid + 1; else hi = mid; }
    int r1 = lo;

    float a = 0.f, b = 0.f, w0 = 0.f, w1 = 0.f;
    if (lane < HID) {
        a = g_ab[lane]; b = g_ab[HID + lane];
        w0 = fcW[lane * 2 + 0]; w1 = fcW[lane * 2 + 1];
    }
    float pool = 0.f;
    for (int n = r0; n < r1; n++) {
        float v = (lane < HID) ? g_tmp[(size_t)n * HID + lane] * a + b : 0.f;
        pool += fmaxf(v, 0.f);
    }
    float o0 = pool * w0, o1 = pool * w1;
#pragma unroll
    for (int o = 16; o; o >>= 1) {
        o0 += __shfl_down_sync(0xffffffff, o0, o);
        o1 += __shfl_down_sync(0xffffffff, o1, o);
    }
    if (lane == 0) {
        out[gid * 2 + 0] = o0 + fcb[0];
        out[gid * 2 + 1] = o1 + fcb[1];
    }
}

extern "C" void kernel_launch(void* const* d_in, const int* in_sizes, int n_in,
                              void* d_out, int out_size) {
    const float* x     = (const float*)d_in[0];
    const int*   ei    = (const int*)d_in[1];
    const int*   batch = (const int*)d_in[2];
    const float* W1  = (const float*)d_in[3];
    const float* b1  = (const float*)d_in[4];
    const float* g1  = (const float*)d_in[5];
    const float* be1 = (const float*)d_in[6];
    const float* W2  = (const float*)d_in[7];
    const float* b2  = (const float*)d_in[8];
    const float* g2  = (const float*)d_in[9];
    const float* be2 = (const float*)d_in[10];
    const float* W3  = (const float*)d_in[11];
    const float* b3  = (const float*)d_in[12];
    const float* g3  = (const float*)d_in[13];
    const float* be3 = (const float*)d_in[14];
    const float* fcW = (const float*)d_in[15];
    const float* fcb = (const float*)d_in[16];
    float* out = (float*)d_out;

    const int NB1 = (N_NODES + 127) / 128;   // GRP=2: 128 nodes/block -> 782
    const int NB2 = (N_NODES + 63) / 64;     // GRP=4:  64 nodes/block -> 1563

    k_zero_cur<<<NBLK_N, TB>>>();
    k_fill4<<<(N_EDGES / 4 + TB - 1) / TB, TB>>>(ei);
    k_x2h<<<NBLK_N, TB>>>(x);

    // layer 1 (reads g_xh: 32B rows, 2-lane groups)
    k_gin<IN_DIM, 16, 2><<<NB1, TB>>>(W1, b1);
    k_finalize<<<1, 640>>>(g1, be1, NB1);
    k_norm<<<NBLK_N, TB>>>();

    // layer 2 (reads g_hh: 64B rows, 4-lane groups)
    k_gin<HID, 32, 4><<<NB2, TB>>>(W2, b2);
    k_finalize<<<1, 640>>>(g2, be2, NB2);
    k_norm<<<NBLK_N, TB>>>();

    // layer 3
    k_gin<HID, 32, 4><<<NB2, TB>>>(W3, b3);
    k_finalize<<<1, 640>>>(g3, be3, NB2);

    // norm + pool + fc fused (batch sorted -> contiguous ranges)
    k_pool_fc<<<(N_GRAPHS * 32 + TB - 1) / TB, TB>>>(batch, fcW, fcb, out);
}